// round 1
// baseline (speedup 1.0000x reference)
#include <cuda_runtime.h>

#define NT 2
#define NPER 256
#define MAXNEI 128
#define E0 25
#define E1 50
#define E2 100
#define FIT_IN 1600
#define FH 240
#define BB 4
#define NROWS 2048

// scratch: DR matrix, 2048 rows x 1600 = 13.1 MB
__device__ __align__(16) float g_DR[(size_t)NROWS * FIT_IN];

__device__ __forceinline__ float tanhe(float x) {
    float xa = fminf(fmaxf(x, -15.f), 15.f);
    float t = __expf(2.f * xa);
    return __fdividef(t - 1.f, t + 1.f);
}

// ---------------- Kernel A: embedding + xyz einsum + DR ----------------
// shared layout (float offsets)
#define OFF_W0 0        // 25 (pad 28)
#define OFF_B0 28       // 25 (pad 28)
#define OFF_W1 56       // 25*50 = 1250 (pad 1252)
#define OFF_B1 1308     // 50 (pad 52)
#define OFF_W2 1360     // [50][104] = 5200
#define OFF_B2 6560     // 100
#define OFF_H1 6660     // [128][51] = 6528
#define OFF_G  13188    // [128][104] = 13312
#define OFF_BLK 26500   // [128][4] = 512
#define OFF_XYZ 27012   // [4][100] = 400
#define A_SMEM_FLOATS 27412

__global__ void __launch_bounds__(128, 2) emb_dr_kernel(
    const float* __restrict__ Ri,
    const float* __restrict__ eW0, const float* __restrict__ eB0,
    const float* __restrict__ eW1, const float* __restrict__ eB1,
    const float* __restrict__ eW2, const float* __restrict__ eB2)
{
    extern __shared__ float sm[];
    const int t = threadIdx.x;
    const int blk = blockIdx.x;
    const int n = blk & 255;
    const int b = (blk >> 8) & 3;
    const int i = blk >> 10;

    const float* ri_base = Ri + ((size_t)((b * NT + i) * NPER + n)) * (NT * MAXNEI) * 4;

    float accXYZ[4] = {0.f, 0.f, 0.f, 0.f};

    for (int j = 0; j < NT; ++j) {
        __syncthreads();  // previous iteration's einsum reads must finish
        const int e = i * NT + j;
        // cooperative weight staging
        if (t < E0) { sm[OFF_W0 + t] = eW0[e * E0 + t]; sm[OFF_B0 + t] = eB0[e * E0 + t]; }
        for (int x = t; x < E0 * E1; x += 128) sm[OFF_W1 + x] = eW1[e * (E0 * E1) + x];
        if (t < E1) sm[OFF_B1 + t] = eB1[e * E1 + t];
        for (int x = t; x < E1 * E2; x += 128) {
            int k = x / E2, g = x - k * E2;
            sm[OFF_W2 + k * 104 + g] = eW2[e * (E1 * E2) + x];
        }
        if (t < E2) sm[OFF_B2 + t] = eB2[e * E2 + t];
        float4 rv = *(const float4*)(ri_base + (size_t)(j * MAXNEI + t) * 4);
        *(float4*)&sm[OFF_BLK + t * 4] = rv;
        __syncthreads();

        // ---- per-neighbor embedding MLP ----
        const float s = rv.x;
        float h0[E0];
#pragma unroll
        for (int k = 0; k < E0; ++k)
            h0[k] = tanhe(fmaf(s, sm[OFF_W0 + k], sm[OFF_B0 + k]));

        float h1[E1];
#pragma unroll
        for (int g = 0; g < E1; g += 2) {
            float a0 = sm[OFF_B1 + g], a1 = sm[OFF_B1 + g + 1];
#pragma unroll
            for (int k = 0; k < E0; ++k) {
                float2 w = *(const float2*)&sm[OFF_W1 + k * E1 + g];
                a0 = fmaf(h0[k], w.x, a0);
                a1 = fmaf(h0[k], w.y, a1);
            }
            h1[g]     = tanhe(a0) + h0[g % E0];
            h1[g + 1] = tanhe(a1) + h0[(g + 1) % E0];
            sm[OFF_H1 + t * 51 + g]     = h1[g];
            sm[OFF_H1 + t * 51 + g + 1] = h1[g + 1];
        }

#pragma unroll 1
        for (int g4 = 0; g4 < E2; g4 += 4) {
            float a0 = sm[OFF_B2 + g4 + 0];
            float a1 = sm[OFF_B2 + g4 + 1];
            float a2 = sm[OFF_B2 + g4 + 2];
            float a3 = sm[OFF_B2 + g4 + 3];
#pragma unroll
            for (int k = 0; k < E1; ++k) {
                float4 w = *(const float4*)&sm[OFF_W2 + k * 104 + g4];
                float hk = h1[k];
                a0 = fmaf(hk, w.x, a0);
                a1 = fmaf(hk, w.y, a1);
                a2 = fmaf(hk, w.z, a2);
                a3 = fmaf(hk, w.w, a3);
            }
            int q0 = g4 + 0; if (q0 >= E1) q0 -= E1;
            int q1 = g4 + 1; if (q1 >= E1) q1 -= E1;
            int q2 = g4 + 2; if (q2 >= E1) q2 -= E1;
            int q3 = g4 + 3; if (q3 >= E1) q3 -= E1;
            const int rb = OFF_H1 + t * 51;
            float4 outv;
            outv.x = tanhe(a0) + sm[rb + q0];
            outv.y = tanhe(a1) + sm[rb + q1];
            outv.z = tanhe(a2) + sm[rb + q2];
            outv.w = tanhe(a3) + sm[rb + q3];
            *(float4*)&sm[OFF_G + t * 104 + g4] = outv;
        }
        __syncthreads();

        // ---- xyz einsum: thread t (<100) owns g = t, c = 0..3 in regs ----
        if (t < E2) {
#pragma unroll 4
            for (int m = 0; m < 128; ++m) {
                float4 bv = *(const float4*)&sm[OFF_BLK + m * 4];
                float gv = sm[OFF_G + m * 104 + t];
                accXYZ[0] = fmaf(bv.x, gv, accXYZ[0]);
                accXYZ[1] = fmaf(bv.y, gv, accXYZ[1]);
                accXYZ[2] = fmaf(bv.z, gv, accXYZ[2]);
                accXYZ[3] = fmaf(bv.w, gv, accXYZ[3]);
            }
        }
    }

    if (t < E2) {
        const float invn = 1.f / 256.f;
        sm[OFF_XYZ + 0 * E2 + t] = accXYZ[0] * invn;
        sm[OFF_XYZ + 1 * E2 + t] = accXYZ[1] * invn;
        sm[OFF_XYZ + 2 * E2 + t] = accXYZ[2] * invn;
        sm[OFF_XYZ + 3 * E2 + t] = accXYZ[3] * invn;
    }
    __syncthreads();

    const int row = (i * BB + b) * NPER + n;
    float* drow = g_DR + (size_t)row * FIT_IN;
#pragma unroll 1
    for (int o = 0; o < 13; ++o) {
        int idx = t + o * 128;
        if (idx < FIT_IN) {
            int g = idx >> 4, h = idx & 15;
            float a = sm[OFF_XYZ + 0 * E2 + g] * sm[OFF_XYZ + 0 * E2 + h];
            a = fmaf(sm[OFF_XYZ + 1 * E2 + g], sm[OFF_XYZ + 1 * E2 + h], a);
            a = fmaf(sm[OFF_XYZ + 2 * E2 + g], sm[OFF_XYZ + 2 * E2 + h], a);
            a = fmaf(sm[OFF_XYZ + 3 * E2 + g], sm[OFF_XYZ + 3 * E2 + h], a);
            drow[idx] = a;
        }
    }
}

// ---------------- Kernel B: fit network (4 chained layers) ----------------
#define B_TILE 16
#define B_THREADS 256
#define OFF_IN 0
#define OFF_HA (B_TILE * FIT_IN)        // 25600
#define OFF_HB (OFF_HA + B_TILE * FH)   // 29440
#define B_SMEM_FLOATS (OFF_HB + B_TILE * FH)  // 33280

__global__ void __launch_bounds__(256, 1) fit_kernel(
    const float* __restrict__ W0, const float* __restrict__ b0,
    const float* __restrict__ W1, const float* __restrict__ b1,
    const float* __restrict__ W2, const float* __restrict__ b2,
    const float* __restrict__ W3, const float* __restrict__ b3,
    float* __restrict__ out)
{
    extern __shared__ float sm[];
    const int tid = threadIdx.x;
    const int i = blockIdx.x >> 6;
    const int tile = blockIdx.x & 63;
    const int r0 = tile * B_TILE;

    const float* W0g = W0 + (size_t)i * FIT_IN * FH;
    const float* W1g = W1 + (size_t)i * FH * FH;
    const float* W2g = W2 + (size_t)i * FH * FH;
    const float* W3g = W3 + (size_t)i * FH;
    const float* b0g = b0 + i * FH;
    const float* b1g = b1 + i * FH;
    const float* b2g = b2 + i * FH;
    const float  b3v = b3[i];

    // load DR tile (16 rows x 1600)
    {
        const float4* src = (const float4*)(g_DR + ((size_t)(i * (BB * NPER) + r0)) * FIT_IN);
        float4* dst = (float4*)&sm[OFF_IN];
        for (int x = tid; x < B_TILE * FIT_IN / 4; x += B_THREADS) dst[x] = src[x];
    }
    __syncthreads();

    const int o = tid;
    const int oc = o < FH ? o : FH - 1;
    float acc[B_TILE];

    // layer 0: 1600 -> 240, tanh
    {
        float bias = b0g[oc];
#pragma unroll
        for (int r = 0; r < B_TILE; ++r) acc[r] = bias;
#pragma unroll 1
        for (int k = 0; k < FIT_IN; k += 4) {
            float w0 = W0g[(size_t)(k + 0) * FH + oc];
            float w1 = W0g[(size_t)(k + 1) * FH + oc];
            float w2 = W0g[(size_t)(k + 2) * FH + oc];
            float w3 = W0g[(size_t)(k + 3) * FH + oc];
#pragma unroll
            for (int r = 0; r < B_TILE; ++r) {
                float4 d = *(const float4*)&sm[OFF_IN + r * FIT_IN + k];
                acc[r] = fmaf(d.x, w0, acc[r]);
                acc[r] = fmaf(d.y, w1, acc[r]);
                acc[r] = fmaf(d.z, w2, acc[r]);
                acc[r] = fmaf(d.w, w3, acc[r]);
            }
        }
        if (o < FH) {
#pragma unroll
            for (int r = 0; r < B_TILE; ++r) sm[OFF_HA + r * FH + o] = tanhe(acc[r]);
        }
    }
    __syncthreads();

    // layer 1: 240 -> 240, tanh + residual  (sHa -> sHb)
    {
        float bias = b1g[oc];
#pragma unroll
        for (int r = 0; r < B_TILE; ++r) acc[r] = bias;
#pragma unroll 1
        for (int k = 0; k < FH; k += 4) {
            float w0 = W1g[(k + 0) * FH + oc];
            float w1 = W1g[(k + 1) * FH + oc];
            float w2 = W1g[(k + 2) * FH + oc];
            float w3 = W1g[(k + 3) * FH + oc];
#pragma unroll
            for (int r = 0; r < B_TILE; ++r) {
                float4 d = *(const float4*)&sm[OFF_HA + r * FH + k];
                acc[r] = fmaf(d.x, w0, acc[r]);
                acc[r] = fmaf(d.y, w1, acc[r]);
                acc[r] = fmaf(d.z, w2, acc[r]);
                acc[r] = fmaf(d.w, w3, acc[r]);
            }
        }
        if (o < FH) {
#pragma unroll
            for (int r = 0; r < B_TILE; ++r)
                sm[OFF_HB + r * FH + o] = tanhe(acc[r]) + sm[OFF_HA + r * FH + o];
        }
    }
    __syncthreads();

    // layer 2: 240 -> 240, tanh + residual  (sHb -> sHa)
    {
        float bias = b2g[oc];
#pragma unroll
        for (int r = 0; r < B_TILE; ++r) acc[r] = bias;
#pragma unroll 1
        for (int k = 0; k < FH; k += 4) {
            float w0 = W2g[(k + 0) * FH + oc];
            float w1 = W2g[(k + 1) * FH + oc];
            float w2 = W2g[(k + 2) * FH + oc];
            float w3 = W2g[(k + 3) * FH + oc];
#pragma unroll
            for (int r = 0; r < B_TILE; ++r) {
                float4 d = *(const float4*)&sm[OFF_HB + r * FH + k];
                acc[r] = fmaf(d.x, w0, acc[r]);
                acc[r] = fmaf(d.y, w1, acc[r]);
                acc[r] = fmaf(d.z, w2, acc[r]);
                acc[r] = fmaf(d.w, w3, acc[r]);
            }
        }
        if (o < FH) {
#pragma unroll
            for (int r = 0; r < B_TILE; ++r)
                sm[OFF_HA + r * FH + o] = tanhe(acc[r]) + sm[OFF_HB + r * FH + o];
        }
    }
    __syncthreads();

    // final: 240 -> 1 (warp per 2 rows)
    const int wi = tid >> 5, lane = tid & 31;
#pragma unroll 1
    for (int rr = 0; rr < 2; ++rr) {
        int r = wi * 2 + rr;
        float p = 0.f;
        for (int o2 = lane; o2 < FH; o2 += 32) p = fmaf(sm[OFF_HA + r * FH + o2], W3g[o2], p);
#pragma unroll
        for (int sd = 16; sd > 0; sd >>= 1) p += __shfl_down_sync(0xffffffffu, p, sd);
        if (lane == 0) {
            int rowg = r0 + r;
            int bb = rowg >> 8, nn = rowg & 255;
            out[(bb * NT + i) * NPER + nn] = p + b3v;
        }
    }
}

// ---------------- launch ----------------
extern "C" void kernel_launch(void* const* d_in, const int* in_sizes, int n_in,
                              void* d_out, int out_size) {
    const float* Ri  = (const float*)d_in[0];
    const float* eW0 = (const float*)d_in[1];
    const float* eB0 = (const float*)d_in[2];
    const float* eW1 = (const float*)d_in[3];
    const float* eB1 = (const float*)d_in[4];
    const float* eW2 = (const float*)d_in[5];
    const float* eB2 = (const float*)d_in[6];
    const float* fW0 = (const float*)d_in[7];
    const float* fB0 = (const float*)d_in[8];
    const float* fW1 = (const float*)d_in[9];
    const float* fB1 = (const float*)d_in[10];
    const float* fW2 = (const float*)d_in[11];
    const float* fB2 = (const float*)d_in[12];
    const float* fW3 = (const float*)d_in[13];
    const float* fB3 = (const float*)d_in[14];
    float* out = (float*)d_out;

    cudaFuncSetAttribute(emb_dr_kernel, cudaFuncAttributeMaxDynamicSharedMemorySize,
                         A_SMEM_FLOATS * 4);
    cudaFuncSetAttribute(fit_kernel, cudaFuncAttributeMaxDynamicSharedMemorySize,
                         B_SMEM_FLOATS * 4);

    emb_dr_kernel<<<NROWS, 128, A_SMEM_FLOATS * 4>>>(Ri, eW0, eB0, eW1, eB1, eW2, eB2);
    fit_kernel<<<128, B_THREADS, B_SMEM_FLOATS * 4>>>(fW0, fB0, fW1, fB1, fW2, fB2, fW3, fB3, out);
}

// round 2
// speedup vs baseline: 1.1069x; 1.1069x over previous
#include <cuda_runtime.h>

#define NT 2
#define NPER 256
#define MAXNEI 128
#define E0 25
#define E1 50
#define E2 100
#define FIT_IN 1600
#define FH 240
#define BB 4
#define NROWS 2048

// scratch: DR matrix, 2048 rows x 1600 = 13.1 MB
__device__ __align__(16) float g_DR[(size_t)NROWS * FIT_IN];

__device__ __forceinline__ float tanhe(float x) {
    float xa = fminf(fmaxf(x, -15.f), 15.f);
    float t = __expf(2.f * xa);
    return __fdividef(t - 1.f, t + 1.f);
}

__device__ __forceinline__ unsigned smaddr(const void* p) {
    unsigned a;
    asm("{.reg .u64 t; cvta.to.shared.u64 t, %1; cvt.u32.u64 %0, t;}" : "=r"(a) : "l"(p));
    return a;
}
__device__ __forceinline__ void cp16(unsigned dst, const void* src) {
    asm volatile("cp.async.ca.shared.global [%0], [%1], 16;" :: "r"(dst), "l"(src));
}
__device__ __forceinline__ void cp_commit() {
    asm volatile("cp.async.commit_group;" ::: "memory");
}

// ---------------- Kernel A: embedding + xyz einsum + DR ----------------
#define OFF_W0 0
#define OFF_B0 28
#define OFF_W1 56
#define OFF_B1 1308
#define OFF_W2 1360
#define OFF_B2 6560
#define OFF_H1 6660
#define OFF_G  13188
#define OFF_BLK 26500
#define OFF_XYZ 27012
#define A_SMEM_FLOATS 27412

__global__ void __launch_bounds__(128, 2) emb_dr_kernel(
    const float* __restrict__ Ri,
    const float* __restrict__ eW0, const float* __restrict__ eB0,
    const float* __restrict__ eW1, const float* __restrict__ eB1,
    const float* __restrict__ eW2, const float* __restrict__ eB2)
{
    extern __shared__ float sm[];
    const int t = threadIdx.x;
    const int blk = blockIdx.x;
    const int n = blk & 255;
    const int b = (blk >> 8) & 3;
    const int i = blk >> 10;

    const float* ri_base = Ri + ((size_t)((b * NT + i) * NPER + n)) * (NT * MAXNEI) * 4;

    float accXYZ[4] = {0.f, 0.f, 0.f, 0.f};

    for (int j = 0; j < NT; ++j) {
        __syncthreads();
        const int e = i * NT + j;
        if (t < E0) { sm[OFF_W0 + t] = eW0[e * E0 + t]; sm[OFF_B0 + t] = eB0[e * E0 + t]; }
        for (int x = t; x < E0 * E1; x += 128) sm[OFF_W1 + x] = eW1[e * (E0 * E1) + x];
        if (t < E1) sm[OFF_B1 + t] = eB1[e * E1 + t];
        for (int x = t; x < E1 * E2; x += 128) {
            int k = x / E2, g = x - k * E2;
            sm[OFF_W2 + k * 104 + g] = eW2[e * (E1 * E2) + x];
        }
        if (t < E2) sm[OFF_B2 + t] = eB2[e * E2 + t];
        float4 rv = *(const float4*)(ri_base + (size_t)(j * MAXNEI + t) * 4);
        *(float4*)&sm[OFF_BLK + t * 4] = rv;
        __syncthreads();

        const float s = rv.x;
        float h0[E0];
#pragma unroll
        for (int k = 0; k < E0; ++k)
            h0[k] = tanhe(fmaf(s, sm[OFF_W0 + k], sm[OFF_B0 + k]));

        float h1[E1];
#pragma unroll
        for (int g = 0; g < E1; g += 2) {
            float a0 = sm[OFF_B1 + g], a1 = sm[OFF_B1 + g + 1];
#pragma unroll
            for (int k = 0; k < E0; ++k) {
                float2 w = *(const float2*)&sm[OFF_W1 + k * E1 + g];
                a0 = fmaf(h0[k], w.x, a0);
                a1 = fmaf(h0[k], w.y, a1);
            }
            h1[g]     = tanhe(a0) + h0[g % E0];
            h1[g + 1] = tanhe(a1) + h0[(g + 1) % E0];
            sm[OFF_H1 + t * 51 + g]     = h1[g];
            sm[OFF_H1 + t * 51 + g + 1] = h1[g + 1];
        }

#pragma unroll 1
        for (int g4 = 0; g4 < E2; g4 += 4) {
            float a0 = sm[OFF_B2 + g4 + 0];
            float a1 = sm[OFF_B2 + g4 + 1];
            float a2 = sm[OFF_B2 + g4 + 2];
            float a3 = sm[OFF_B2 + g4 + 3];
#pragma unroll
            for (int k = 0; k < E1; ++k) {
                float4 w = *(const float4*)&sm[OFF_W2 + k * 104 + g4];
                float hk = h1[k];
                a0 = fmaf(hk, w.x, a0);
                a1 = fmaf(hk, w.y, a1);
                a2 = fmaf(hk, w.z, a2);
                a3 = fmaf(hk, w.w, a3);
            }
            int q0 = g4 + 0; if (q0 >= E1) q0 -= E1;
            int q1 = g4 + 1; if (q1 >= E1) q1 -= E1;
            int q2 = g4 + 2; if (q2 >= E1) q2 -= E1;
            int q3 = g4 + 3; if (q3 >= E1) q3 -= E1;
            const int rb = OFF_H1 + t * 51;
            float4 outv;
            outv.x = tanhe(a0) + sm[rb + q0];
            outv.y = tanhe(a1) + sm[rb + q1];
            outv.z = tanhe(a2) + sm[rb + q2];
            outv.w = tanhe(a3) + sm[rb + q3];
            *(float4*)&sm[OFF_G + t * 104 + g4] = outv;
        }
        __syncthreads();

        if (t < E2) {
#pragma unroll 4
            for (int m = 0; m < 128; ++m) {
                float4 bv = *(const float4*)&sm[OFF_BLK + m * 4];
                float gv = sm[OFF_G + m * 104 + t];
                accXYZ[0] = fmaf(bv.x, gv, accXYZ[0]);
                accXYZ[1] = fmaf(bv.y, gv, accXYZ[1]);
                accXYZ[2] = fmaf(bv.z, gv, accXYZ[2]);
                accXYZ[3] = fmaf(bv.w, gv, accXYZ[3]);
            }
        }
    }

    if (t < E2) {
        const float invn = 1.f / 256.f;
        sm[OFF_XYZ + 0 * E2 + t] = accXYZ[0] * invn;
        sm[OFF_XYZ + 1 * E2 + t] = accXYZ[1] * invn;
        sm[OFF_XYZ + 2 * E2 + t] = accXYZ[2] * invn;
        sm[OFF_XYZ + 3 * E2 + t] = accXYZ[3] * invn;
    }
    __syncthreads();

    const int row = (i * BB + b) * NPER + n;
    float* drow = g_DR + (size_t)row * FIT_IN;
#pragma unroll 1
    for (int o = 0; o < 13; ++o) {
        int idx = t + o * 128;
        if (idx < FIT_IN) {
            int g = idx >> 4, h = idx & 15;
            float a = sm[OFF_XYZ + 0 * E2 + g] * sm[OFF_XYZ + 0 * E2 + h];
            a = fmaf(sm[OFF_XYZ + 1 * E2 + g], sm[OFF_XYZ + 1 * E2 + h], a);
            a = fmaf(sm[OFF_XYZ + 2 * E2 + g], sm[OFF_XYZ + 2 * E2 + h], a);
            a = fmaf(sm[OFF_XYZ + 3 * E2 + g], sm[OFF_XYZ + 3 * E2 + h], a);
            drow[idx] = a;
        }
    }
}

// ---------------- Kernel B v2: register-tiled chained fit GEMM ----------------
// smem layout (floats):
//   dr   [16][1600]            25600
//   w_s  [2][32][240]          15360
//   actA [16][240]              3840
//   actB [16][240]              3840
#define KT 32
#define SM_DR   0
#define SM_WS   25600
#define SM_ACTA (25600 + 2 * KT * FH)
#define SM_ACTB (SM_ACTA + 16 * FH)
#define B_SMEM_FLOATS (SM_ACTB + 16 * FH)   // 48640 floats = 194560 B

#define ROWF(r, D, WV) \
    acc[r][0] = fmaf(D, WV.x, acc[r][0]); acc[r][1] = fmaf(D, WV.y, acc[r][1]); \
    acc[r][2] = fmaf(D, WV.z, acc[r][2]); acc[r][3] = fmaf(D, WV.w, acc[r][3]);
#define STEP(WV, D0, D1, D2, D3) ROWF(0, D0, WV) ROWF(1, D1, WV) ROWF(2, D2, WV) ROWF(3, D3, WV)

// One layer: out[16][240] = act(dpan[16][K] @ Wg[K][240] + bg) (+ res)
__device__ __forceinline__ void run_layer(
    const float* __restrict__ Wg, const float* __restrict__ bg, int K,
    const float* __restrict__ dpan, int dstride,
    float* w_s, const float* __restrict__ res, float* __restrict__ outp,
    int tid, int ry, int c0)
{
    float acc[4][4];
    {
        float4 bv = *(const float4*)&bg[c0];
#pragma unroll
        for (int r = 0; r < 4; ++r) {
            acc[r][0] = bv.x; acc[r][1] = bv.y; acc[r][2] = bv.z; acc[r][3] = bv.w;
        }
    }

    const int T = (K + KT - 1) / KT;

    // prologue: stage tile 0
    {
        int len0 = K < KT ? K : KT;
        for (int x = tid; x < len0 * 60; x += 256) {
            int kk = x / 60, seg = x - kk * 60;
            cp16(smaddr(w_s + kk * FH + seg * 4), Wg + (size_t)kk * FH + seg * 4);
        }
        cp_commit();
    }

#pragma unroll 1
    for (int t = 0; t < T; ++t) {
        const int kbase = t * KT;
        int len = K - kbase; if (len > KT) len = KT;

        if (t + 1 < T) {
            float* wnext = w_s + ((t + 1) & 1) * (KT * FH);
            const int kb2 = kbase + KT;
            int len2 = K - kb2; if (len2 > KT) len2 = KT;
            for (int x = tid; x < len2 * 60; x += 256) {
                int kk = x / 60, seg = x - kk * 60;
                cp16(smaddr(wnext + kk * FH + seg * 4), Wg + (size_t)(kb2 + kk) * FH + seg * 4);
            }
            cp_commit();
            asm volatile("cp.async.wait_group 1;" ::: "memory");
        } else {
            asm volatile("cp.async.wait_group 0;" ::: "memory");
        }
        __syncthreads();

        const float* wt = w_s + (t & 1) * (KT * FH);
        const float* dp = dpan + (size_t)(4 * ry) * dstride + kbase;
#pragma unroll 2
        for (int k4 = 0; k4 < len; k4 += 4) {
            float4 dv0 = *(const float4*)(dp + 0 * dstride + k4);
            float4 dv1 = *(const float4*)(dp + 1 * dstride + k4);
            float4 dv2 = *(const float4*)(dp + 2 * dstride + k4);
            float4 dv3 = *(const float4*)(dp + 3 * dstride + k4);
            float4 wv0 = *(const float4*)(wt + (k4 + 0) * FH + c0);
            float4 wv1 = *(const float4*)(wt + (k4 + 1) * FH + c0);
            float4 wv2 = *(const float4*)(wt + (k4 + 2) * FH + c0);
            float4 wv3 = *(const float4*)(wt + (k4 + 3) * FH + c0);
            STEP(wv0, dv0.x, dv1.x, dv2.x, dv3.x)
            STEP(wv1, dv0.y, dv1.y, dv2.y, dv3.y)
            STEP(wv2, dv0.z, dv1.z, dv2.z, dv3.z)
            STEP(wv3, dv0.w, dv1.w, dv2.w, dv3.w)
        }
        __syncthreads();
    }

    // epilogue: activation (+residual), write out. cx>=60 threads duplicate
    // col group 59 (same values) — benign identical writes.
#pragma unroll
    for (int r = 0; r < 4; ++r) {
        int row = 4 * ry + r;
        float4 o;
        o.x = tanhe(acc[r][0]);
        o.y = tanhe(acc[r][1]);
        o.z = tanhe(acc[r][2]);
        o.w = tanhe(acc[r][3]);
        if (res) {
            float4 rv = *(const float4*)&res[row * FH + c0];
            o.x += rv.x; o.y += rv.y; o.z += rv.z; o.w += rv.w;
        }
        *(float4*)&outp[row * FH + c0] = o;
    }
}

__global__ void __launch_bounds__(256, 1) fit_kernel(
    const float* __restrict__ W0, const float* __restrict__ b0,
    const float* __restrict__ W1, const float* __restrict__ b1,
    const float* __restrict__ W2, const float* __restrict__ b2,
    const float* __restrict__ W3, const float* __restrict__ b3,
    float* __restrict__ out)
{
    extern __shared__ float sm[];
    float* dr   = sm + SM_DR;
    float* w_s  = sm + SM_WS;
    float* actA = sm + SM_ACTA;
    float* actB = sm + SM_ACTB;

    const int tid = threadIdx.x;
    const int i = blockIdx.x >> 6;
    const int r0 = (blockIdx.x & 63) * 16;
    const int ry = tid >> 6;
    const int cx = tid & 63;
    const int cc = (cx < 60) ? cx : 59;
    const int c0 = cc * 4;

    const float* W0g = W0 + (size_t)i * FIT_IN * FH;
    const float* W1g = W1 + (size_t)i * FH * FH;
    const float* W2g = W2 + (size_t)i * FH * FH;
    const float* W3g = W3 + (size_t)i * FH;
    const float* b0g = b0 + i * FH;
    const float* b1g = b1 + i * FH;
    const float* b2g = b2 + i * FH;
    const float  b3v = b3[i];

    // stage DR panel (16 rows contiguous = 25600 floats) via cp.async
    {
        const float* drg = g_DR + (size_t)(i * (BB * NPER) + r0) * FIT_IN;
        for (int x = tid; x < (16 * FIT_IN) / 4; x += 256)
            cp16(smaddr(dr + x * 4), drg + x * 4);
        cp_commit();
    }

    // layer 0: 1600 -> 240, tanh
    run_layer(W0g, b0g, FIT_IN, dr, FIT_IN, w_s, nullptr, actA, tid, ry, c0);
    __syncthreads();
    // layer 1: 240 -> 240, tanh + residual
    run_layer(W1g, b1g, FH, actA, FH, w_s, actA, actB, tid, ry, c0);
    __syncthreads();
    // layer 2: 240 -> 240, tanh + residual
    run_layer(W2g, b2g, FH, actB, FH, w_s, actB, actA, tid, ry, c0);
    __syncthreads();

    // final: 240 -> 1, warp per 2 rows
    const int wi = tid >> 5, lane = tid & 31;
#pragma unroll 1
    for (int rr = 0; rr < 2; ++rr) {
        int r = wi * 2 + rr;
        float p = 0.f;
        for (int o2 = lane; o2 < FH; o2 += 32) p = fmaf(actA[r * FH + o2], W3g[o2], p);
#pragma unroll
        for (int sd = 16; sd > 0; sd >>= 1) p += __shfl_down_sync(0xffffffffu, p, sd);
        if (lane == 0) {
            int rowg = r0 + r;
            int bb = rowg >> 8, nn = rowg & 255;
            out[(bb * NT + i) * NPER + nn] = p + b3v;
        }
    }
}

// ---------------- launch ----------------
extern "C" void kernel_launch(void* const* d_in, const int* in_sizes, int n_in,
                              void* d_out, int out_size) {
    const float* Ri  = (const float*)d_in[0];
    const float* eW0 = (const float*)d_in[1];
    const float* eB0 = (const float*)d_in[2];
    const float* eW1 = (const float*)d_in[3];
    const float* eB1 = (const float*)d_in[4];
    const float* eW2 = (const float*)d_in[5];
    const float* eB2 = (const float*)d_in[6];
    const float* fW0 = (const float*)d_in[7];
    const float* fB0 = (const float*)d_in[8];
    const float* fW1 = (const float*)d_in[9];
    const float* fB1 = (const float*)d_in[10];
    const float* fW2 = (const float*)d_in[11];
    const float* fB2 = (const float*)d_in[12];
    const float* fW3 = (const float*)d_in[13];
    const float* fB3 = (const float*)d_in[14];
    float* out = (float*)d_out;

    cudaFuncSetAttribute(emb_dr_kernel, cudaFuncAttributeMaxDynamicSharedMemorySize,
                         A_SMEM_FLOATS * 4);
    cudaFuncSetAttribute(fit_kernel, cudaFuncAttributeMaxDynamicSharedMemorySize,
                         B_SMEM_FLOATS * 4);

    emb_dr_kernel<<<NROWS, 128, A_SMEM_FLOATS * 4>>>(Ri, eW0, eB0, eW1, eB1, eW2, eB2);
    fit_kernel<<<128, 256, B_SMEM_FLOATS * 4>>>(fW0, fB0, fW1, fB1, fW2, fB2, fW3, fB3, out);
}